// round 10
// baseline (speedup 1.0000x reference)
#include <cuda_runtime.h>
#include <cuda_bf16.h>

#define T_TOKENS 8192
#define D_DIM    768
#define N_EXP    8
#define CAP      2048

// Scratch (device allocation is forbidden)
__device__ int   g_expert_index[T_TOKENS];
__device__ float g_expert_gate[T_TOKENS];

// ---------------------------------------------------------------------------
// 1) Fused router + zero-fill. (Unchanged from the passing 190.9us version —
//    fill measured ~6.5 TB/s, near the HBM-write roofline.)
//    Blocks 0..1023 (8 warps each) first route 8 tokens apiece:
//      logits = x[t] @ W  (768x8 dot), softmax top-1:
//      index = argmax(logits) (first max wins), gate = 1/sum(exp(l - lmax)).
//    Then ALL blocks join a grid-stride float4 streaming zero-fill of the
//    full 1 GiB output.
// ---------------------------------------------------------------------------
__global__ void __launch_bounds__(256)
fill_route_kernel(const float* __restrict__ x,
                  const float* __restrict__ W,
                  float4* __restrict__ out, long long n4) {
    if (blockIdx.x < T_TOKENS / 8) {
        int lane  = threadIdx.x & 31;
        int token = blockIdx.x * 8 + (threadIdx.x >> 5);

        const float* xr = x + (size_t)token * D_DIM;
        float acc[N_EXP];
#pragma unroll
        for (int e = 0; e < N_EXP; e++) acc[e] = 0.0f;

#pragma unroll 4
        for (int d = lane; d < D_DIM; d += 32) {
            float xv = __ldg(xr + d);
            const float* wr = W + (size_t)d * N_EXP;
#pragma unroll
            for (int e = 0; e < N_EXP; e++) acc[e] += xv * __ldg(wr + e);
        }

#pragma unroll
        for (int e = 0; e < N_EXP; e++) {
#pragma unroll
            for (int o = 16; o > 0; o >>= 1)
                acc[e] += __shfl_xor_sync(0xFFFFFFFFu, acc[e], o);
        }

        if (lane == 0) {
            float m = acc[0];
            int   mi = 0;
#pragma unroll
            for (int e = 1; e < N_EXP; e++) {
                if (acc[e] > m) { m = acc[e]; mi = e; }  // first max (jax top_k)
            }
            float s = 0.0f;
#pragma unroll
            for (int e = 0; e < N_EXP; e++) s += __expf(acc[e] - m);
            g_expert_index[token] = mi;
            g_expert_gate[token]  = 1.0f / s;
        }
    }

    // --- fill phase: everyone; 4x unrolled grid-stride streaming stores ---
    const float4 z = make_float4(0.f, 0.f, 0.f, 0.f);
    long long stride = (long long)gridDim.x * blockDim.x;
    long long i      = (long long)blockIdx.x * blockDim.x + threadIdx.x;
    for (; i + 3 * stride < n4; i += 4 * stride) {
        __stcs(&out[i],              z);
        __stcs(&out[i +     stride], z);
        __stcs(&out[i + 2 * stride], z);
        __stcs(&out[i + 3 * stride], z);
    }
    for (; i < n4; i += stride) __stcs(&out[i], z);
}

// ---------------------------------------------------------------------------
// 2) Packed 8-expert scan + scatter. ONE block of 1024 threads.
//    The 8 expert counters are packed as 8 x 16-bit fields in two uint64s
//    (experts 0-3 in lo, 4-7 in hi). One block-wide inclusive scan of the
//    packed pair per 1024-token chunk ranks ALL experts simultaneously —
//    8x less scan work than the old one-block-per-expert version (25.2us,
//    grid=8, all pipes idle). No overflow: each field's final value <= 8192.
//    Token t (expert e, inclusive 1-indexed slot p) kept iff p < 2048:
//      dispatch[t, e, p] = 1.0
//      combined[t, e, p] = gate[t]
//    Layout: out = [dispatch (T,E,C) | combined (T,E,C)], row-major.
// ---------------------------------------------------------------------------
__global__ void __launch_bounds__(1024)
scan_scatter_kernel(float* __restrict__ out) {
    const int tid  = threadIdx.x;
    const int lane = tid & 31;
    const int wid  = tid >> 5;

    typedef unsigned long long u64;
    __shared__ u64 wsum_lo[32], wsum_hi[32];
    __shared__ u64 s_carry_lo, s_carry_hi;
    if (tid == 0) { s_carry_lo = 0; s_carry_hi = 0; }
    __syncthreads();

    for (int base = 0; base < T_TOKENS; base += 1024) {
        int t = base + tid;
        int e = g_expert_index[t];

        // one-hot packed increment
        u64 v_lo = (e < 4) ? (1ULL << (16 * e))       : 0ULL;
        u64 v_hi = (e >= 4) ? (1ULL << (16 * (e - 4))) : 0ULL;

        // warp inclusive scan of the packed pair
#pragma unroll
        for (int o = 1; o < 32; o <<= 1) {
            u64 nlo = __shfl_up_sync(0xFFFFFFFFu, v_lo, o);
            u64 nhi = __shfl_up_sync(0xFFFFFFFFu, v_hi, o);
            if (lane >= o) { v_lo += nlo; v_hi += nhi; }
        }
        if (lane == 31) { wsum_lo[wid] = v_lo; wsum_hi[wid] = v_hi; }
        __syncthreads();

        // scan the 32 warp totals in warp 0
        if (tid < 32) {
            u64 wlo = wsum_lo[tid];
            u64 whi = wsum_hi[tid];
#pragma unroll
            for (int o = 1; o < 32; o <<= 1) {
                u64 nlo = __shfl_up_sync(0xFFFFFFFFu, wlo, o);
                u64 nhi = __shfl_up_sync(0xFFFFFFFFu, whi, o);
                if (tid >= o) { wlo += nlo; whi += nhi; }
            }
            wsum_lo[tid] = wlo; wsum_hi[tid] = whi;
        }
        __syncthreads();

        u64 inc_lo = s_carry_lo + v_lo + ((wid > 0) ? wsum_lo[wid - 1] : 0ULL);
        u64 inc_hi = s_carry_hi + v_hi + ((wid > 0) ? wsum_hi[wid - 1] : 0ULL);

        // extract this token's inclusive 1-indexed rank within its expert
        int p = (e < 4) ? (int)((inc_lo >> (16 * e)) & 0xFFFF)
                        : (int)((inc_hi >> (16 * (e - 4))) & 0xFFFF);

        if (p < CAP) {
            size_t idx = (size_t)t * (N_EXP * CAP) + (size_t)e * CAP + (size_t)p;
            out[idx] = 1.0f;                                              // dispatch
            out[idx + (size_t)T_TOKENS * N_EXP * CAP] = g_expert_gate[t]; // combined
        }
        __syncthreads();

        if (tid == 0) { s_carry_lo += wsum_lo[31]; s_carry_hi += wsum_hi[31]; }
        __syncthreads();
    }
}

// ---------------------------------------------------------------------------
extern "C" void kernel_launch(void* const* d_in, const int* in_sizes, int n_in,
                              void* d_out, int out_size) {
    const float* x = (const float*)d_in[0];   // (8192, 768) f32
    const float* W = (const float*)d_in[1];   // (768, 8) f32
    float* out = (float*)d_out;               // 2 * 8192*8*2048 f32

    fill_route_kernel<<<8192, 256>>>(x, W, (float4*)out, (long long)out_size / 4);
    scan_scatter_kernel<<<1, 1024>>>(out);
}

// round 13
// speedup vs baseline: 1.0229x; 1.0229x over previous
#include <cuda_runtime.h>
#include <cuda_bf16.h>

#define T_TOKENS 8192
#define D_DIM    768
#define N_EXP    8
#define CAP      2048

// Scratch (device allocation is forbidden)
__device__ int   g_expert_index[T_TOKENS];
__device__ float g_expert_gate[T_TOKENS];

// ---------------------------------------------------------------------------
// 1) Fused router + zero-fill. (Unchanged: fill measured ~6.5 TB/s, ~82% of
//    HBM spec — near the write roofline.)
// ---------------------------------------------------------------------------
__global__ void __launch_bounds__(256)
fill_route_kernel(const float* __restrict__ x,
                  const float* __restrict__ W,
                  float4* __restrict__ out, long long n4) {
    if (blockIdx.x < T_TOKENS / 8) {
        int lane  = threadIdx.x & 31;
        int token = blockIdx.x * 8 + (threadIdx.x >> 5);

        const float* xr = x + (size_t)token * D_DIM;
        float acc[N_EXP];
#pragma unroll
        for (int e = 0; e < N_EXP; e++) acc[e] = 0.0f;

#pragma unroll 4
        for (int d = lane; d < D_DIM; d += 32) {
            float xv = __ldg(xr + d);
            const float* wr = W + (size_t)d * N_EXP;
#pragma unroll
            for (int e = 0; e < N_EXP; e++) acc[e] += xv * __ldg(wr + e);
        }

#pragma unroll
        for (int e = 0; e < N_EXP; e++) {
#pragma unroll
            for (int o = 16; o > 0; o >>= 1)
                acc[e] += __shfl_xor_sync(0xFFFFFFFFu, acc[e], o);
        }

        if (lane == 0) {
            float m = acc[0];
            int   mi = 0;
#pragma unroll
            for (int e = 1; e < N_EXP; e++) {
                if (acc[e] > m) { m = acc[e]; mi = e; }  // first max (jax top_k)
            }
            float s = 0.0f;
#pragma unroll
            for (int e = 0; e < N_EXP; e++) s += __expf(acc[e] - m);
            g_expert_index[token] = mi;
            g_expert_gate[token]  = 1.0f / s;
        }
    }

    // --- fill phase: everyone; 4x unrolled grid-stride streaming stores ---
    const float4 z = make_float4(0.f, 0.f, 0.f, 0.f);
    long long stride = (long long)gridDim.x * blockDim.x;
    long long i      = (long long)blockIdx.x * blockDim.x + threadIdx.x;
    for (; i + 3 * stride < n4; i += 4 * stride) {
        __stcs(&out[i],              z);
        __stcs(&out[i +     stride], z);
        __stcs(&out[i + 2 * stride], z);
        __stcs(&out[i + 3 * stride], z);
    }
    for (; i < n4; i += stride) __stcs(&out[i], z);
}

// ---------------------------------------------------------------------------
// 2) Single-round packed scan + scatter. ONE block, 1024 threads, 8 tokens
//    per thread (contiguous). All loads front-batched (int4/float4), ONE
//    block-wide exclusive scan of the 8x16-bit packed counter pair
//    (experts 0-3 in lo u64, 4-7 in hi u64), then a serial 8-token local walk
//    reconstructs each token's inclusive 1-indexed rank and scatters the two
//    nonzeros. 2 barriers total (vs 32 in the chunked version whose serial
//    carry chain measured 21.9us at issue=23%).
//    Keep iff p < 2048. Layout: out = [dispatch (T,E,C) | combined (T,E,C)].
// ---------------------------------------------------------------------------
__global__ void __launch_bounds__(1024)
scan_scatter_kernel(float* __restrict__ out) {
    const int tid  = threadIdx.x;
    const int lane = tid & 31;
    const int wid  = tid >> 5;

    typedef unsigned long long u64;
    __shared__ u64 wsum_lo[32], wsum_hi[32];

    // --- front-batched loads: 8 indices + 8 gates ---
    const int4*   gi = (const int4*)g_expert_index;
    const float4* gg = (const float4*)g_expert_gate;
    int4   ia = gi[tid * 2], ib = gi[tid * 2 + 1];
    float4 ga = gg[tid * 2], gb = gg[tid * 2 + 1];
    int   e[8] = {ia.x, ia.y, ia.z, ia.w, ib.x, ib.y, ib.z, ib.w};
    float g[8] = {ga.x, ga.y, ga.z, ga.w, gb.x, gb.y, gb.z, gb.w};

    // --- local packed totals ---
    u64 v_lo = 0, v_hi = 0;
#pragma unroll
    for (int k = 0; k < 8; k++) {
        if (e[k] < 4) v_lo += 1ULL << (16 * e[k]);
        else          v_hi += 1ULL << (16 * (e[k] - 4));
    }

    // --- block-wide exclusive scan of the packed pair ---
    u64 s_lo = v_lo, s_hi = v_hi;            // warp inclusive scan
#pragma unroll
    for (int o = 1; o < 32; o <<= 1) {
        u64 nlo = __shfl_up_sync(0xFFFFFFFFu, s_lo, o);
        u64 nhi = __shfl_up_sync(0xFFFFFFFFu, s_hi, o);
        if (lane >= o) { s_lo += nlo; s_hi += nhi; }
    }
    if (lane == 31) { wsum_lo[wid] = s_lo; wsum_hi[wid] = s_hi; }
    __syncthreads();

    if (tid < 32) {                          // scan the 32 warp totals
        u64 wlo = wsum_lo[tid], whi = wsum_hi[tid];
#pragma unroll
        for (int o = 1; o < 32; o <<= 1) {
            u64 nlo = __shfl_up_sync(0xFFFFFFFFu, wlo, o);
            u64 nhi = __shfl_up_sync(0xFFFFFFFFu, whi, o);
            if (tid >= o) { wlo += nlo; whi += nhi; }
        }
        wsum_lo[tid] = wlo; wsum_hi[tid] = whi;
    }
    __syncthreads();

    // exclusive prefix for this thread's first token
    u64 run_lo = (s_lo - v_lo) + ((wid > 0) ? wsum_lo[wid - 1] : 0ULL);
    u64 run_hi = (s_hi - v_hi) + ((wid > 0) ? wsum_hi[wid - 1] : 0ULL);

    // --- serial local walk: inclusive ranks + scatter ---
    const size_t HALF = (size_t)T_TOKENS * N_EXP * CAP;
#pragma unroll
    for (int k = 0; k < 8; k++) {
        int ek = e[k];
        int p;
        if (ek < 4) { run_lo += 1ULL << (16 * ek);
                      p = (int)((run_lo >> (16 * ek)) & 0xFFFF); }
        else        { run_hi += 1ULL << (16 * (ek - 4));
                      p = (int)((run_hi >> (16 * (ek - 4))) & 0xFFFF); }
        if (p < CAP) {
            int t = tid * 8 + k;
            size_t idx = (size_t)t * (N_EXP * CAP) + (size_t)ek * CAP + (size_t)p;
            out[idx]        = 1.0f;    // dispatch
            out[idx + HALF] = g[k];    // combined
        }
    }
}

// ---------------------------------------------------------------------------
extern "C" void kernel_launch(void* const* d_in, const int* in_sizes, int n_in,
                              void* d_out, int out_size) {
    const float* x = (const float*)d_in[0];   // (8192, 768) f32
    const float* W = (const float*)d_in[1];   // (768, 8) f32
    float* out = (float*)d_out;               // 2 * 8192*8*2048 f32

    fill_route_kernel<<<8192, 256>>>(x, W, (float4*)out, (long long)out_size / 4);
    scan_scatter_kernel<<<1, 1024>>>(out);
}